// round 1
// baseline (speedup 1.0000x reference)
#include <cuda_runtime.h>

#define B_   256
#define T_   128
#define SIG_ 64
#define MET_ 32
#define H_   256
#define F_   16
#define NC   1040   // 4*H + F concatenated gate columns: [i|ste|c|o|fre]
#define NP   1088   // padded to 17*64 for tiling

// ---- persistent scratch (device globals; no allocation) ----
__device__ float g_Wcat[96 * NP];
__device__ float g_Ucat[H_ * NP];
__device__ float g_bcat[NP];
__device__ float g_Xz[T_ * B_ * NP];      // precomputed input projections + bias
__device__ float g_Z[2][B_ * NP];         // per-step recurrent GEMM partials (K split in 2)
__device__ float g_h[B_ * H_];
__device__ float g_Sre[B_ * F_ * H_];     // layout [b][f][h] for coalesced access
__device__ float g_Sim[B_ * F_ * H_];

__device__ __forceinline__ float hsig(float x) {
    return __saturatef(x * (1.0f / 6.0f) + 0.5f);
}

// ---------------------------------------------------------------------------
// Setup: build concatenated weight/bias matrices, zero the recurrent state.
// Runs every replay (deterministic).
// ---------------------------------------------------------------------------
__global__ void setup_kernel(
    const float* __restrict__ Wi_s,  const float* __restrict__ Wste_s,
    const float* __restrict__ Wfre_s,const float* __restrict__ Wc_s,
    const float* __restrict__ Wo_s,
    const float* __restrict__ Wi_m,  const float* __restrict__ Wste_m,
    const float* __restrict__ Wfre_m,const float* __restrict__ Wc_m,
    const float* __restrict__ Wo_m,
    const float* __restrict__ Ui,    const float* __restrict__ Uste,
    const float* __restrict__ Ufre,  const float* __restrict__ Uc,
    const float* __restrict__ Uo,
    const float* __restrict__ bi,    const float* __restrict__ bste,
    const float* __restrict__ bfre,  const float* __restrict__ bc,
    const float* __restrict__ bo)
{
    int tid = blockIdx.x * blockDim.x + threadIdx.x;
    int nth = gridDim.x * blockDim.x;

    for (int idx = tid; idx < 96 * NP; idx += nth) {
        int k = idx / NP, col = idx - k * NP;
        float v = 0.f;
        if (col < 1024) {
            int g = col >> 8, j = col & 255;
            if (k < 64) {
                const float* W = (g == 0) ? Wi_s : (g == 1) ? Wste_s : (g == 2) ? Wc_s : Wo_s;
                v = W[k * H_ + j];
            } else {
                const float* W = (g == 0) ? Wi_m : (g == 1) ? Wste_m : (g == 2) ? Wc_m : Wo_m;
                v = W[(k - 64) * H_ + j];
            }
        } else if (col < NC) {
            int j = col - 1024;
            v = (k < 64) ? Wfre_s[k * F_ + j] : Wfre_m[(k - 64) * F_ + j];
        }
        g_Wcat[idx] = v;
    }

    for (int idx = tid; idx < H_ * NP; idx += nth) {
        int k = idx / NP, col = idx - k * NP;
        float v = 0.f;
        if (col < 1024) {
            int g = col >> 8, j = col & 255;
            const float* U = (g == 0) ? Ui : (g == 1) ? Uste : (g == 2) ? Uc : Uo;
            v = U[k * H_ + j];
        } else if (col < NC) {
            v = Ufre[k * F_ + (col - 1024)];
        }
        g_Ucat[idx] = v;
    }

    for (int col = tid; col < NP; col += nth) {
        float v = 0.f;
        if      (col < 256)  v = bi[col];
        else if (col < 512)  v = bste[col - 256];
        else if (col < 768)  v = bc[col - 512];
        else if (col < 1024) v = bo[col - 768];
        else if (col < NC)   v = bfre[col - 1024];
        g_bcat[col] = v;
    }

    for (int i = tid; i < B_ * H_; i += nth) g_h[i] = 0.f;
    for (int i = tid; i < B_ * F_ * H_; i += nth) { g_Sre[i] = 0.f; g_Sim[i] = 0.f; }
}

// ---------------------------------------------------------------------------
// GEMM tiles: BM x BN = 64x64, BK = 32, 256 threads, 4x4 microtile.
// ---------------------------------------------------------------------------
#define BM 64
#define BN 64
#define BK 32

// Precompute: Xz[t*B+b][col] = [signal|metmast] @ Wcat + bcat.  M=32768, K=96.
__global__ __launch_bounds__(256) void gemm_pre(
    const float* __restrict__ signal, const float* __restrict__ metmast)
{
    __shared__ float As[BK][BM + 4];
    __shared__ float Bs[BK][BN];
    int m0 = blockIdx.x * BM, n0 = blockIdx.y * BN;
    int tid = threadIdx.x;
    int tx = tid & 15, ty = tid >> 4;
    float acc[4][4];
    #pragma unroll
    for (int i = 0; i < 4; i++)
        #pragma unroll
        for (int j = 0; j < 4; j++) acc[i][j] = 0.f;

    for (int kk = 0; kk < 96; kk += BK) {
        #pragma unroll
        for (int l = 0; l < 8; l++) {
            int idx = tid + l * 256;
            int ml = idx >> 5, kl = idx & 31;
            int m = m0 + ml; int b = m & 255; int t = m >> 8;
            int k = kk + kl;
            As[kl][ml] = (k < SIG_) ? signal[(b * T_ + t) * SIG_ + k]
                                    : metmast[(b * T_ + t) * MET_ + (k - SIG_)];
        }
        #pragma unroll
        for (int l = 0; l < 8; l++) {
            int idx = tid + l * 256;
            int kl = idx >> 6, nl = idx & 63;
            Bs[kl][nl] = g_Wcat[(kk + kl) * NP + n0 + nl];
        }
        __syncthreads();
        #pragma unroll
        for (int k = 0; k < BK; k++) {
            float4 a4 = *(const float4*)&As[k][ty * 4];
            float4 b4 = *(const float4*)&Bs[k][tx * 4];
            float ar[4] = {a4.x, a4.y, a4.z, a4.w};
            float br[4] = {b4.x, b4.y, b4.z, b4.w};
            #pragma unroll
            for (int i = 0; i < 4; i++)
                #pragma unroll
                for (int j = 0; j < 4; j++) acc[i][j] += ar[i] * br[j];
        }
        __syncthreads();
    }
    #pragma unroll
    for (int i = 0; i < 4; i++) {
        int m = m0 + ty * 4 + i;
        #pragma unroll
        for (int j = 0; j < 4; j++) {
            int n = n0 + tx * 4 + j;
            g_Xz[m * NP + n] = acc[i][j] + g_bcat[n];
        }
    }
}

// Per-step recurrent GEMM: Z[z][b][col] = h @ Ucat (K split into 2 halves).
// Grid (4, 17, 2).
__global__ __launch_bounds__(256) void gemm_step()
{
    __shared__ float As[BK][BM + 4];
    __shared__ float Bs[BK][BN];
    int m0 = blockIdx.x * BM, n0 = blockIdx.y * BN;
    int kbase = blockIdx.z * 128;
    int tid = threadIdx.x;
    int tx = tid & 15, ty = tid >> 4;
    float acc[4][4];
    #pragma unroll
    for (int i = 0; i < 4; i++)
        #pragma unroll
        for (int j = 0; j < 4; j++) acc[i][j] = 0.f;

    for (int kk = kbase; kk < kbase + 128; kk += BK) {
        #pragma unroll
        for (int l = 0; l < 8; l++) {
            int idx = tid + l * 256;
            int ml = idx >> 5, kl = idx & 31;
            As[kl][ml] = g_h[(m0 + ml) * H_ + kk + kl];
        }
        #pragma unroll
        for (int l = 0; l < 8; l++) {
            int idx = tid + l * 256;
            int kl = idx >> 6, nl = idx & 63;
            Bs[kl][nl] = g_Ucat[(kk + kl) * NP + n0 + nl];
        }
        __syncthreads();
        #pragma unroll
        for (int k = 0; k < BK; k++) {
            float4 a4 = *(const float4*)&As[k][ty * 4];
            float4 b4 = *(const float4*)&Bs[k][tx * 4];
            float ar[4] = {a4.x, a4.y, a4.z, a4.w};
            float br[4] = {b4.x, b4.y, b4.z, b4.w};
            #pragma unroll
            for (int i = 0; i < 4; i++)
                #pragma unroll
                for (int j = 0; j < 4; j++) acc[i][j] += ar[i] * br[j];
        }
        __syncthreads();
    }
    float* Zout = g_Z[blockIdx.z];
    #pragma unroll
    for (int i = 0; i < 4; i++) {
        int m = m0 + ty * 4 + i;
        #pragma unroll
        for (int j = 0; j < 4; j++) {
            int n = n0 + tx * 4 + j;
            Zout[m * NP + n] = acc[i][j];
        }
    }
}

// ---------------------------------------------------------------------------
// Per-step fused gates + SFM state update.  t = 1..T.  Block = one batch row.
// ---------------------------------------------------------------------------
__global__ __launch_bounds__(256) void step_update(
    int t, const float* __restrict__ Ua, const float* __restrict__ ba)
{
    int b = blockIdx.x;
    int h = threadIdx.x;
    __shared__ float fre_sh[F_], csh[F_], ssh[F_], ua_sh[F_];

    const float* xrow = g_Xz + ((size_t)(t - 1) * B_ + b) * NP;
    const float* z0 = g_Z[0] + b * NP;
    const float* z1 = g_Z[1] + b * NP;

    if (h < F_) {
        float zf = xrow[1024 + h] + z0[1024 + h] + z1[1024 + h];
        fre_sh[h] = hsig(zf);
        int p = (t * h) & 15;                 // exact phase: 2*pi*t*f/16 mod 2*pi
        csh[h] = cospif((float)p * 0.125f);
        ssh[h] = sinpif((float)p * 0.125f);
        ua_sh[h] = Ua[h];
    }
    __syncthreads();

    float zi = xrow[h]       + z0[h]       + z1[h];
    float zs = xrow[256 + h] + z0[256 + h] + z1[256 + h];
    float zc = xrow[512 + h] + z0[512 + h] + z1[512 + h];
    float zo = xrow[768 + h] + z0[768 + h] + z1[768 + h];

    float ig  = hsig(zi);
    float ste = hsig(zs);
    float og  = hsig(zo);
    float cg  = ig * tanhf(zc);

    float acc = 0.f;
    int base = (b * F_) * H_ + h;
    #pragma unroll
    for (int f = 0; f < F_; f++) {
        int idx = base + f * H_;
        float ff = ste * fre_sh[f];
        float Sr = ff * g_Sre[idx] + cg * csh[f];
        float Si = ff * g_Sim[idx] + cg * ssh[f];
        g_Sre[idx] = Sr;
        g_Sim[idx] = Si;
        acc += (Sr * Sr + Si * Si) * ua_sh[f];
    }
    float a = tanhf(acc + ba[h]);
    g_h[b * H_ + h] = og * a;
}

// ---------------------------------------------------------------------------
// Final projection: out[b] = (h[b,:]·W_p + b_p) * fc_w + fc_b.
// ---------------------------------------------------------------------------
__global__ void final_kernel(
    const float* __restrict__ Wp, const float* __restrict__ bp,
    const float* __restrict__ fcw, const float* __restrict__ fcb,
    float* __restrict__ out)
{
    int b = blockIdx.x;
    int lane = threadIdx.x;
    float s = 0.f;
    for (int l = lane; l < H_; l += 32) s += g_h[b * H_ + l] * Wp[l];
    #pragma unroll
    for (int o = 16; o; o >>= 1) s += __shfl_down_sync(0xffffffffu, s, o);
    if (lane == 0) out[b] = (s + bp[0]) * fcw[0] + fcb[0];
}

// ---------------------------------------------------------------------------
extern "C" void kernel_launch(void* const* d_in, const int* in_sizes, int n_in,
                              void* d_out, int out_size)
{
    (void)in_sizes; (void)n_in; (void)out_size;
    const float* signal  = (const float*)d_in[0];
    const float* metmast = (const float*)d_in[1];
    const float* Wi_s    = (const float*)d_in[2];
    const float* Wste_s  = (const float*)d_in[3];
    const float* Wfre_s  = (const float*)d_in[4];
    const float* Wc_s    = (const float*)d_in[5];
    const float* Wo_s    = (const float*)d_in[6];
    const float* Wi_m    = (const float*)d_in[7];
    const float* Wste_m  = (const float*)d_in[8];
    const float* Wfre_m  = (const float*)d_in[9];
    const float* Wc_m    = (const float*)d_in[10];
    const float* Wo_m    = (const float*)d_in[11];
    const float* Ui      = (const float*)d_in[12];
    const float* bi      = (const float*)d_in[13];
    const float* Uste    = (const float*)d_in[14];
    const float* bste    = (const float*)d_in[15];
    const float* Ufre    = (const float*)d_in[16];
    const float* bfre    = (const float*)d_in[17];
    const float* Uc      = (const float*)d_in[18];
    const float* bc      = (const float*)d_in[19];
    const float* Uo      = (const float*)d_in[20];
    const float* bo      = (const float*)d_in[21];
    const float* Ua      = (const float*)d_in[22];
    const float* ba      = (const float*)d_in[23];
    const float* Wp      = (const float*)d_in[24];
    const float* bp      = (const float*)d_in[25];
    const float* fcw     = (const float*)d_in[26];
    const float* fcb     = (const float*)d_in[27];
    float* out = (float*)d_out;

    setup_kernel<<<512, 256>>>(Wi_s, Wste_s, Wfre_s, Wc_s, Wo_s,
                               Wi_m, Wste_m, Wfre_m, Wc_m, Wo_m,
                               Ui, Uste, Ufre, Uc, Uo,
                               bi, bste, bfre, bc, bo);

    gemm_pre<<<dim3(T_ * B_ / BM, NP / BN), 256>>>(signal, metmast);

    for (int t = 1; t <= T_; t++) {
        gemm_step<<<dim3(B_ / BM, NP / BN, 2), 256>>>();
        step_update<<<B_, H_>>>(t, Ua, ba);
    }

    final_kernel<<<B_, 32>>>(Wp, bp, fcw, fcb, out);
}

// round 5
// speedup vs baseline: 1.1592x; 1.1592x over previous
#include <cuda_runtime.h>

#define B_   256
#define T_   128
#define SIG_ 64
#define MET_ 32
#define H_   256
#define F_   16
#define NC   1040   // 4*H + F concatenated gate columns: [i|ste|c|o|fre]
#define NP   1088   // padded to 17*64
#define NB   136    // persistent blocks (<= 148 SMs, guaranteed co-resident)

// ---- persistent scratch (device globals; no allocation) ----
__device__ float g_Wcat[96 * NP];
__device__ float g_Ucat[H_ * NP];
__device__ float g_bcat[NP];
__device__ float g_Xz[(size_t)T_ * B_ * NP];   // precomputed input projections + bias
__device__ float g_Z[2][B_ * NP];              // per-step recurrent GEMM partials
__device__ float g_h[B_ * H_];
__device__ unsigned g_barcnt;

typedef unsigned long long ull;

__device__ __forceinline__ ull pk2(float x, float y) {
    ull r; asm("mov.b64 %0, {%1, %2};" : "=l"(r) : "f"(x), "f"(y)); return r;
}
__device__ __forceinline__ void fma2(ull& d, ull a, ull b) {
    asm("fma.rn.f32x2 %0, %1, %2, %0;" : "+l"(d) : "l"(a), "l"(b));
}
__device__ __forceinline__ void unpk(ull v, float& x, float& y) {
    asm("mov.b64 {%0, %1}, %2;" : "=f"(x), "=f"(y) : "l"(v));
}
__device__ __forceinline__ float hsig(float x) {
    return __saturatef(x * (1.0f / 6.0f) + 0.5f);
}

// Software grid barrier: monotonic counter, no reset race.
// Spin uses nanosleep to avoid hammering the L2 atomic slice.
__device__ __forceinline__ void gbar(unsigned target) {
    __syncthreads();
    if (threadIdx.x == 0) {
        __threadfence();
        atomicAdd(&g_barcnt, 1u);
        unsigned v;
        do {
            asm volatile("ld.volatile.global.u32 %0, [%1];"
                         : "=r"(v) : "l"(&g_barcnt));
            if (v >= target) break;
            __nanosleep(64);
        } while (true);
        __threadfence();
    }
    __syncthreads();
}

// ---------------------------------------------------------------------------
// Setup: concatenated weights/bias, zero h, zero barrier counter.
// ---------------------------------------------------------------------------
__global__ void setup_kernel(
    const float* __restrict__ Wi_s,  const float* __restrict__ Wste_s,
    const float* __restrict__ Wfre_s,const float* __restrict__ Wc_s,
    const float* __restrict__ Wo_s,
    const float* __restrict__ Wi_m,  const float* __restrict__ Wste_m,
    const float* __restrict__ Wfre_m,const float* __restrict__ Wc_m,
    const float* __restrict__ Wo_m,
    const float* __restrict__ Ui,    const float* __restrict__ Uste,
    const float* __restrict__ Ufre,  const float* __restrict__ Uc,
    const float* __restrict__ Uo,
    const float* __restrict__ bi,    const float* __restrict__ bste,
    const float* __restrict__ bfre,  const float* __restrict__ bc,
    const float* __restrict__ bo)
{
    int tid = blockIdx.x * blockDim.x + threadIdx.x;
    int nth = gridDim.x * blockDim.x;
    if (tid == 0) g_barcnt = 0u;

    for (int idx = tid; idx < 96 * NP; idx += nth) {
        int k = idx / NP, col = idx - k * NP;
        float v = 0.f;
        if (col < 1024) {
            int g = col >> 8, j = col & 255;
            if (k < 64) {
                const float* W = (g == 0) ? Wi_s : (g == 1) ? Wste_s : (g == 2) ? Wc_s : Wo_s;
                v = W[k * H_ + j];
            } else {
                const float* W = (g == 0) ? Wi_m : (g == 1) ? Wste_m : (g == 2) ? Wc_m : Wo_m;
                v = W[(k - 64) * H_ + j];
            }
        } else if (col < NC) {
            int j = col - 1024;
            v = (k < 64) ? Wfre_s[k * F_ + j] : Wfre_m[(k - 64) * F_ + j];
        }
        g_Wcat[idx] = v;
    }

    for (int idx = tid; idx < H_ * NP; idx += nth) {
        int k = idx / NP, col = idx - k * NP;
        float v = 0.f;
        if (col < 1024) {
            int g = col >> 8, j = col & 255;
            const float* U = (g == 0) ? Ui : (g == 1) ? Uste : (g == 2) ? Uc : Uo;
            v = U[k * H_ + j];
        } else if (col < NC) {
            v = Ufre[k * F_ + (col - 1024)];
        }
        g_Ucat[idx] = v;
    }

    for (int col = tid; col < NP; col += nth) {
        float v = 0.f;
        if      (col < 256)  v = bi[col];
        else if (col < 512)  v = bste[col - 256];
        else if (col < 768)  v = bc[col - 512];
        else if (col < 1024) v = bo[col - 768];
        else if (col < NC)   v = bfre[col - 1024];
        g_bcat[col] = v;
    }

    for (int i = tid; i < B_ * H_; i += nth) g_h[i] = 0.f;
}

// ---------------------------------------------------------------------------
// Precompute Xz = [signal|metmast] @ Wcat + bcat.  M=32768, K=96.  f32x2 FMA.
// ---------------------------------------------------------------------------
__global__ __launch_bounds__(256) void gemm_pre(
    const float* __restrict__ signal, const float* __restrict__ metmast)
{
    __shared__ float As[32][68];
    __shared__ float Bs[32][64];
    int m0 = blockIdx.x * 64, n0 = blockIdx.y * 64;
    int tid = threadIdx.x;
    int tx = tid & 15, ty = tid >> 4;
    ull acc[4][2];
    #pragma unroll
    for (int i = 0; i < 4; i++) { acc[i][0] = 0ull; acc[i][1] = 0ull; }

    for (int kk = 0; kk < 96; kk += 32) {
        #pragma unroll
        for (int l = 0; l < 8; l++) {
            int idx = tid + l * 256;
            int ml = idx >> 5, kl = idx & 31;
            int m = m0 + ml; int b = m & 255; int t = m >> 8;
            int k = kk + kl;
            As[kl][ml] = (k < SIG_) ? signal[(b * T_ + t) * SIG_ + k]
                                    : metmast[(b * T_ + t) * MET_ + (k - SIG_)];
        }
        #pragma unroll
        for (int l = 0; l < 8; l++) {
            int idx = tid + l * 256;
            int kl = idx >> 6, nl = idx & 63;
            Bs[kl][nl] = g_Wcat[(kk + kl) * NP + n0 + nl];
        }
        __syncthreads();
        #pragma unroll
        for (int k = 0; k < 32; k++) {
            float4 a4 = *(const float4*)&As[k][ty * 4];
            float4 b4 = *(const float4*)&Bs[k][tx * 4];
            ull b0 = pk2(b4.x, b4.y), b1 = pk2(b4.z, b4.w);
            ull aa;
            aa = pk2(a4.x, a4.x); fma2(acc[0][0], aa, b0); fma2(acc[0][1], aa, b1);
            aa = pk2(a4.y, a4.y); fma2(acc[1][0], aa, b0); fma2(acc[1][1], aa, b1);
            aa = pk2(a4.z, a4.z); fma2(acc[2][0], aa, b0); fma2(acc[2][1], aa, b1);
            aa = pk2(a4.w, a4.w); fma2(acc[3][0], aa, b0); fma2(acc[3][1], aa, b1);
        }
        __syncthreads();
    }
    #pragma unroll
    for (int i = 0; i < 4; i++) {
        int m = m0 + ty * 4 + i, n = n0 + tx * 4;
        float x0, x1, x2, x3;
        unpk(acc[i][0], x0, x1); unpk(acc[i][1], x2, x3);
        float4 o = make_float4(x0 + g_bcat[n], x1 + g_bcat[n + 1],
                               x2 + g_bcat[n + 2], x3 + g_bcat[n + 3]);
        *(float4*)&g_Xz[(size_t)m * NP + n] = o;
    }
}

// ---------------------------------------------------------------------------
// Persistent kernel: all 128 time steps.  S-state lives in registers.
// Each step: (GEMM phase, all 136 blocks) -> gbar -> (update phase) -> gbar.
// ---------------------------------------------------------------------------
__global__ __launch_bounds__(512, 1) void persist(
    const float* __restrict__ Ua, const float* __restrict__ ba)
{
    __shared__ float As[32][66];
    __shared__ float Bs[32][64];
    __shared__ float fre_sh[2][16];
    __shared__ float csh[16], ssh[16], ua_sh[16];

    int tid = threadIdx.x;
    int blk = blockIdx.x;
    // GEMM tile assignment: 4 m-tiles x 17 n-tiles x 2 k-splits = 136
    int r = blk % 68, ks = blk / 68;
    int m0 = (r & 3) * 64, n0 = (r >> 2) * 64;
    int kbase = ks * 128;
    int tx = tid & 15, ty = tid >> 4;

    int gid = blk * 512 + tid;
    int b = gid >> 8, h = gid & 255;
    bool has_state = (blk < 128);

    float Sre[16], Sim[16];
    #pragma unroll
    for (int f = 0; f < 16; f++) { Sre[f] = 0.f; Sim[f] = 0.f; }

    if (tid < 16) ua_sh[tid] = Ua[tid];

    unsigned epoch = 0;

    for (int t = 1; t <= T_; t++) {
        if (t > 1) {
            // ---- GEMM phase: Z[ks] = h @ Ucat[kbase:kbase+128, :] ----
            ull acc00 = 0, acc01 = 0, acc10 = 0, acc11 = 0;
            for (int kk = 0; kk < 128; kk += 32) {
                #pragma unroll
                for (int l = 0; l < 4; l++) {
                    int idx = tid + l * 512;
                    int ml = idx >> 5, kl = idx & 31;
                    As[kl][ml] = __ldcg(&g_h[(m0 + ml) * H_ + kbase + kk + kl]);
                }
                #pragma unroll
                for (int l = 0; l < 4; l++) {
                    int idx = tid + l * 512;
                    int kl = idx >> 6, nl = idx & 63;
                    Bs[kl][nl] = g_Ucat[(kbase + kk + kl) * NP + n0 + nl];
                }
                __syncthreads();
                #pragma unroll
                for (int k = 0; k < 32; k++) {
                    float2 a2 = *(const float2*)&As[k][ty * 2];
                    float4 b4 = *(const float4*)&Bs[k][tx * 4];
                    ull b0 = pk2(b4.x, b4.y), b1 = pk2(b4.z, b4.w);
                    ull aa = pk2(a2.x, a2.x);
                    fma2(acc00, aa, b0); fma2(acc01, aa, b1);
                    aa = pk2(a2.y, a2.y);
                    fma2(acc10, aa, b0); fma2(acc11, aa, b1);
                }
                __syncthreads();
            }
            {
                int m = m0 + ty * 2, n = n0 + tx * 4;
                float x0, x1, x2, x3;
                unpk(acc00, x0, x1); unpk(acc01, x2, x3);
                __stcg((float4*)&g_Z[ks][m * NP + n], make_float4(x0, x1, x2, x3));
                unpk(acc10, x0, x1); unpk(acc11, x2, x3);
                __stcg((float4*)&g_Z[ks][(m + 1) * NP + n], make_float4(x0, x1, x2, x3));
            }
            epoch += NB; gbar(epoch);
        }

        // ---- update phase ----
        if (has_state) {
            const float* xrow = g_Xz + ((size_t)(t - 1) * B_ + b) * NP;
            const float* z0 = g_Z[0] + b * NP;
            const float* z1 = g_Z[1] + b * NP;

            if (tid < 32) {
                int f = tid & 15, bb = tid >> 4;
                int bloc = blk * 2 + bb;
                float zf = __ldcs(&g_Xz[((size_t)(t - 1) * B_ + bloc) * NP + 1024 + f]);
                if (t > 1)
                    zf += __ldcg(&g_Z[0][bloc * NP + 1024 + f])
                        + __ldcg(&g_Z[1][bloc * NP + 1024 + f]);
                fre_sh[bb][f] = hsig(zf);
                if (tid < 16) {
                    int p = (t * f) & 15;
                    csh[f] = cospif((float)p * 0.125f);
                    ssh[f] = sinpif((float)p * 0.125f);
                }
            }
            __syncthreads();

            float zi = __ldcs(&xrow[h]);
            float zs = __ldcs(&xrow[256 + h]);
            float zc = __ldcs(&xrow[512 + h]);
            float zo = __ldcs(&xrow[768 + h]);
            if (t > 1) {
                zi += __ldcg(&z0[h])       + __ldcg(&z1[h]);
                zs += __ldcg(&z0[256 + h]) + __ldcg(&z1[256 + h]);
                zc += __ldcg(&z0[512 + h]) + __ldcg(&z1[512 + h]);
                zo += __ldcg(&z0[768 + h]) + __ldcg(&z1[768 + h]);
            }
            float ig  = hsig(zi);
            float ste = hsig(zs);
            float og  = hsig(zo);
            float cg  = ig * tanhf(zc);

            int bb = tid >> 8;
            float acc = 0.f;
            #pragma unroll
            for (int f = 0; f < 16; f++) {
                float ff = ste * fre_sh[bb][f];
                float Sr = ff * Sre[f] + cg * csh[f];
                float Si = ff * Sim[f] + cg * ssh[f];
                Sre[f] = Sr; Sim[f] = Si;
                acc += (Sr * Sr + Si * Si) * ua_sh[f];
            }
            float hn = og * tanhf(acc + ba[h]);
            __stcg(&g_h[b * H_ + h], hn);
        }
        epoch += NB; gbar(epoch);
    }
}

// ---------------------------------------------------------------------------
// Final projection.
// ---------------------------------------------------------------------------
__global__ void final_kernel(
    const float* __restrict__ Wp, const float* __restrict__ bp,
    const float* __restrict__ fcw, const float* __restrict__ fcb,
    float* __restrict__ out)
{
    int b = blockIdx.x;
    int lane = threadIdx.x;
    float s = 0.f;
    for (int l = lane; l < H_; l += 32) s += g_h[b * H_ + l] * Wp[l];
    #pragma unroll
    for (int o = 16; o; o >>= 1) s += __shfl_down_sync(0xffffffffu, s, o);
    if (lane == 0) out[b] = (s + bp[0]) * fcw[0] + fcb[0];
}

// ---------------------------------------------------------------------------
extern "C" void kernel_launch(void* const* d_in, const int* in_sizes, int n_in,
                              void* d_out, int out_size)
{
    (void)in_sizes; (void)n_in; (void)out_size;
    const float* signal  = (const float*)d_in[0];
    const float* metmast = (const float*)d_in[1];
    const float* Wi_s    = (const float*)d_in[2];
    const float* Wste_s  = (const float*)d_in[3];
    const float* Wfre_s  = (const float*)d_in[4];
    const float* Wc_s    = (const float*)d_in[5];
    const float* Wo_s    = (const float*)d_in[6];
    const float* Wi_m    = (const float*)d_in[7];
    const float* Wste_m  = (const float*)d_in[8];
    const float* Wfre_m  = (const float*)d_in[9];
    const float* Wc_m    = (const float*)d_in[10];
    const float* Wo_m    = (const float*)d_in[11];
    const float* Ui      = (const float*)d_in[12];
    const float* bi      = (const float*)d_in[13];
    const float* Uste    = (const float*)d_in[14];
    const float* bste    = (const float*)d_in[15];
    const float* Ufre    = (const float*)d_in[16];
    const float* bfre    = (const float*)d_in[17];
    const float* Uc      = (const float*)d_in[18];
    const float* bc      = (const float*)d_in[19];
    const float* Uo      = (const float*)d_in[20];
    const float* bo      = (const float*)d_in[21];
    const float* Ua      = (const float*)d_in[22];
    const float* ba      = (const float*)d_in[23];
    const float* Wp      = (const float*)d_in[24];
    const float* bp      = (const float*)d_in[25];
    const float* fcw     = (const float*)d_in[26];
    const float* fcb     = (const float*)d_in[27];
    float* out = (float*)d_out;

    setup_kernel<<<512, 256>>>(Wi_s, Wste_s, Wfre_s, Wc_s, Wo_s,
                               Wi_m, Wste_m, Wfre_m, Wc_m, Wo_m,
                               Ui, Uste, Ufre, Uc, Uo,
                               bi, bste, bfre, bc, bo);

    gemm_pre<<<dim3(T_ * B_ / 64, NP / 64), 256>>>(signal, metmast);

    persist<<<NB, 512>>>(Ua, ba);

    final_kernel<<<B_, 32>>>(Wp, bp, fcw, fcb, out);
}